// round 14
// baseline (speedup 1.0000x reference)
#include <cuda_runtime.h>
#include <cuda_fp16.h>
#include <cstdint>
#include <math.h>

// LinkPredictor via mma.sync (HMMA fp16 single-pass, fp32 accum).
// Round 14: MB=64, 128 thr (4 warps, m32n64), B via coalesced LDG from
// fragment-ordered image. smem 49.7 KB -> 4 CTAs/SM = 16 warps with 4-way
// block-boundary overlap. L1 traffic/edge identical to round 13.
// Inputs: 0:z[500000*128]f32 1:edge_index[2*E] (i32 or i64)
//         2:W1[512*128] 3:b1[128] 4:W2[128*64] 5:b2[64] 6:W3[64] 7:b3[1]
// Output: score[E] f32

#define HDIM 128
constexpr int MB      = 64;
constexpr int THREADS = 128;   // 4 warps: 2m x 2n, warp tile m32 x n64

// ---- smem layout ----
constexpr int OFF_PART = 0;          // 512 B
constexpr int PLANE    = 16384;      // 64 rows * 256 B
constexpr int OFF_SRC  = 512;
constexpr int OFF_DST  = OFF_SRC + PLANE;    // 16896
constexpr int OFF_A23  = OFF_DST + PLANE;    // 33280
constexpr int SMEM_TOTAL = OFF_A23 + PLANE;  // 49664 -> 4 CTAs/SM

// fragment-ordered, warp-coalesced weight images
// W1f word idx: [c:4][wn:2][ks:8][t:4][lane:32][r2:4] -> 131072 B
// W2f word idx: [wn:2][ks:8][t:2][lane:32][r2:4]      -> 16384 B
__device__ unsigned char g_W1f[131072];
__device__ unsigned char g_W2f[16384];
__device__ int g_ei_is64;

// ---- helpers ----
__device__ __forceinline__ uint32_t smem_u32(const void* p) {
    uint32_t a;
    asm("{ .reg .u64 t; cvta.to.shared.u64 t, %1; cvt.u32.u64 %0, t; }" : "=r"(a) : "l"(p));
    return a;
}
__device__ __forceinline__ void ldsm4(uint32_t& r0, uint32_t& r1, uint32_t& r2, uint32_t& r3,
                                      uint32_t addr) {
    asm volatile("ldmatrix.sync.aligned.m8n8.x4.shared.b16 {%0,%1,%2,%3}, [%4];"
        : "=r"(r0), "=r"(r1), "=r"(r2), "=r"(r3) : "r"(addr));
}
__device__ __forceinline__ void mma16816(float* c, uint32_t a0, uint32_t a1, uint32_t a2,
                                         uint32_t a3, uint32_t b0, uint32_t b1) {
    asm volatile("mma.sync.aligned.m16n8k16.row.col.f32.f16.f16.f32 "
        "{%0,%1,%2,%3}, {%4,%5,%6,%7}, {%8,%9}, {%0,%1,%2,%3};"
        : "+f"(c[0]), "+f"(c[1]), "+f"(c[2]), "+f"(c[3])
        : "r"(a0), "r"(a1), "r"(a2), "r"(a3), "r"(b0), "r"(b1));
}
// z gather: stream, evict early (keep W image resident in L1)
__device__ __forceinline__ float4 ldg_ef(const float* p) {
    float4 v;
    asm volatile("ld.global.L1::evict_first.v4.f32 {%0,%1,%2,%3}, [%4];"
        : "=f"(v.x), "=f"(v.y), "=f"(v.z), "=f"(v.w) : "l"(p));
    return v;
}
// weight fragments: coalesced 512B/warp, keep resident
__device__ __forceinline__ uint4 ldg_w(const unsigned char* p) {
    uint4 v;
    asm volatile("ld.global.nc.L1::evict_last.v4.u32 {%0,%1,%2,%3}, [%4];"
        : "=r"(v.x), "=r"(v.y), "=r"(v.z), "=r"(v.w) : "l"(p));
    return v;
}

__device__ __host__ __forceinline__ uint32_t aoff(int row, int k) {
    return (uint32_t)(row * 256 + (((k >> 3) ^ (row & 7)) << 4) + (k & 7) * 2);
}
__device__ __forceinline__ uint2 pack4h(float4 v) {
    uint2 r;
    __half2 p0 = __floats2half2_rn(v.x, v.y);
    __half2 p1 = __floats2half2_rn(v.z, v.w);
    r.x = *(uint32_t*)&p0;
    r.y = *(uint32_t*)&p1;
    return r;
}
__device__ __forceinline__ float hfr(uint32_t w, int hi16) {
    return __half2float(__ushort_as_half((uint16_t)(hi16 ? (w >> 16) : (w & 0xffff))));
}

// ---- setup kernel: coalesced fragment-order weights + dtype detect ----
__global__ void prep_weights(const float* __restrict__ W1, const float* __restrict__ W2,
                             const void* ei, int E, int n_nodes) {
    if (blockIdx.x == 0 && threadIdx.x == 0) {
        const long long* e64 = (const long long*)ei;
        int n = (E < 64) ? E : 64;
        int is64 = 1;
        for (int i = 0; i < n; i++) {
            long long v = e64[i];
            if (v < 0 || v >= (long long)n_nodes) { is64 = 0; break; }
        }
        g_ei_is64 = is64;
    }
    int idx = blockIdx.x * 256 + threadIdx.x;
    if (idx < 32768) {
        // word -> (c, wn, ks, t, lane, r2)
        int r2 = idx & 3, lane = (idx >> 2) & 31, t = (idx >> 7) & 3;
        int ks = (idx >> 9) & 7, wn = (idx >> 12) & 1, c = (idx >> 13) & 3;
        int j = t * 2 + (r2 >> 1), r = r2 & 1;
        int n = wn * 64 + j * 8 + (lane >> 2);
        int k = c * 128 + ks * 16 + (lane & 3) * 2 + r * 8;
        __half2 p = __floats2half2_rn(W1[k * 128 + n], W1[(k + 1) * 128 + n]);
        *(uint32_t*)(g_W1f + (size_t)idx * 4) = *(uint32_t*)&p;
    } else if (idx < 32768 + 4096) {
        int i2 = idx - 32768;
        int r2 = i2 & 3, lane = (i2 >> 2) & 31, t = (i2 >> 7) & 1;
        int ks = (i2 >> 8) & 7, wn = (i2 >> 11) & 1;
        int j = t * 2 + (r2 >> 1), r = r2 & 1;
        int n = wn * 32 + j * 8 + (lane >> 2);
        int k = ks * 16 + (lane & 3) * 2 + r * 8;
        __half2 p = __floats2half2_rn(W2[k * 64 + n], W2[(k + 1) * 64 + n]);
        *(uint32_t*)(g_W2f + (size_t)i2 * 4) = *(uint32_t*)&p;
    }
}

// ---- main kernel ----
__global__ __launch_bounds__(THREADS, 4)
void lp_main(const float* __restrict__ z,
             const void* __restrict__ ei_raw,
             const float* __restrict__ b1,
             const float* __restrict__ b2,
             const float* __restrict__ W3,
             const float* __restrict__ b3,
             float* __restrict__ out,
             int E)
{
    extern __shared__ unsigned char sm[];
    const uint32_t smb = smem_u32(sm);
    const int tid  = threadIdx.x;
    const int warp = tid >> 5;
    const int lane = tid & 31;
    const int wm = warp >> 1, wn = warp & 1;
    const int m0 = wm * 32;
    const int eb = blockIdx.x * MB;

    // ---- gather: 16 edges per warp, high-MLP ----
    {
        const int is64 = g_ei_is64;
        const long long* e64 = (const long long*)ei_raw;
        const int*       e32 = (const int*)ei_raw;

        int si[16], di[16];
        #pragma unroll
        for (int i = 0; i < 16; i++) {
            const int e = eb + warp * 16 + i;
            const int ec = (e < E) ? e : (E - 1);
            if (is64) { si[i] = (int)e64[ec]; di[i] = (int)e64[(size_t)E + ec]; }
            else      { si[i] = e32[ec];      di[i] = e32[(size_t)E + ec]; }
        }

        #pragma unroll
        for (int ib = 0; ib < 4; ib++) {
            float4 sv[4], dv[4];
            #pragma unroll
            for (int j = 0; j < 4; j++) {
                sv[j] = ldg_ef(z + (size_t)si[ib * 4 + j] * HDIM + lane * 4);
                dv[j] = ldg_ef(z + (size_t)di[ib * 4 + j] * HDIM + lane * 4);
            }
            #pragma unroll
            for (int j = 0; j < 4; j++) {
                const int r = warp * 16 + ib * 4 + j;
                float4 iv;
                iv.x = sv[j].x * dv[j].x; iv.y = sv[j].y * dv[j].y;
                iv.z = sv[j].z * dv[j].z; iv.w = sv[j].w * dv[j].w;
                const uint32_t o = aoff(r, lane * 4);
                *(uint2*)(sm + OFF_SRC + o) = pack4h(sv[j]);
                *(uint2*)(sm + OFF_DST + o) = pack4h(dv[j]);
                *(uint2*)(sm + OFF_A23 + o) = pack4h(iv);
            }
        }
    }
    __syncthreads();

    // ---- A-side ldmatrix geometry (m32 via two m16 frags) ----
    const int tileA = lane >> 3;
    const int rowA0 = m0 + ((tileA & 1) << 3) + (lane & 7);
    const int rxA   = rowA0 & 7;
    const int kuA   = tileA >> 1;

    float acc[2][32];
    #pragma unroll
    for (int f = 0; f < 2; f++)
        #pragma unroll
        for (int i = 0; i < 32; i++) acc[f][i] = 0.0f;

    static const int AOFS[4] = {OFF_SRC, OFF_DST, OFF_A23, OFF_A23};

    // ---- GEMM1: 4 K-chunks of 128; B via coalesced LDG, double-buffered ----
    #pragma unroll 1
    for (int c = 0; c < 4; c++) {
        if (c == 3) {        // rebuild A23 = |src-dst| (prod reads done)
            __syncthreads();
            #pragma unroll
            for (int t = 0; t < 8; t++) {
                const int idx = tid + t * 128;      // 1024 items of 8 cols
                const int r = idx >> 4, kg = (idx & 15) * 8;
                const uint32_t o = aoff(r, kg);
                const uint4 shv = *(const uint4*)(sm + OFF_SRC + o);
                const uint4 dhv = *(const uint4*)(sm + OFF_DST + o);
                uint4 rv;
                const uint32_t* sp = &shv.x;
                const uint32_t* dp = &dhv.x;
                uint32_t* rp = &rv.x;
                #pragma unroll
                for (int q = 0; q < 4; q++) {
                    float a0 = fabsf(hfr(sp[q],0) - hfr(dp[q],0));
                    float a1 = fabsf(hfr(sp[q],1) - hfr(dp[q],1));
                    __half2 p = __floats2half2_rn(a0, a1);
                    rp[q] = *(uint32_t*)&p;
                }
                *(uint4*)(sm + OFF_A23 + o) = rv;
            }
            __syncthreads();
        }

        const uint32_t ab0 = smb + AOFS[c] + rowA0 * 256;
        const uint32_t ab1 = ab0 + 16 * 256;
        const unsigned char* wp = g_W1f + (size_t)(c * 2 + wn) * 16384 + lane * 16;

        uint4 bq[2][4];
        #pragma unroll
        for (int t = 0; t < 4; t++) bq[0][t] = ldg_w(wp + t * 512);

        #pragma unroll
        for (int ks = 0; ks < 8; ks++) {
            const int cur = ks & 1, nxt = cur ^ 1;
            const uint32_t ao = (uint32_t)((2 * ks + kuA) ^ rxA) << 4;
            uint32_t a0, a1, a2, a3, a4, a5, a6, a7;
            ldsm4(a0, a1, a2, a3, ab0 + ao);
            ldsm4(a4, a5, a6, a7, ab1 + ao);
            if (ks < 7) {
                #pragma unroll
                for (int t = 0; t < 4; t++)
                    bq[nxt][t] = ldg_w(wp + (ks + 1) * 2048 + t * 512);
            }
            const uint32_t* bb = (const uint32_t*)&bq[cur][0];
            #pragma unroll
            for (int j = 0; j < 8; j++)
                mma16816(&acc[0][4*j], a0, a1, a2, a3, bb[2*j], bb[2*j+1]);
            #pragma unroll
            for (int j = 0; j < 8; j++)
                mma16816(&acc[1][4*j], a4, a5, a6, a7, bb[2*j], bb[2*j+1]);
        }
    }

    // ---- epilogue1: h1 = relu(C1 + b1) -> fp16 into A23 ----
    __syncthreads();
    {
        #pragma unroll
        for (int f = 0; f < 2; f++) {
            const int r1 = m0 + f * 16 + (lane >> 2);
            #pragma unroll
            for (int j = 0; j < 8; j++) {
                const int col = wn * 64 + j * 8 + (lane & 3) * 2;
                const float ba = __ldg(b1 + col), bb = __ldg(b1 + col + 1);
                __half2 p0 = __floats2half2_rn(fmaxf(acc[f][4*j]   + ba, 0.0f),
                                               fmaxf(acc[f][4*j+1] + bb, 0.0f));
                __half2 p1 = __floats2half2_rn(fmaxf(acc[f][4*j+2] + ba, 0.0f),
                                               fmaxf(acc[f][4*j+3] + bb, 0.0f));
                *(uint32_t*)(sm + OFF_A23 + aoff(r1, col))     = *(uint32_t*)&p0;
                *(uint32_t*)(sm + OFF_A23 + aoff(r1 + 8, col)) = *(uint32_t*)&p1;
            }
        }
    }
    __syncthreads();

    // ---- GEMM2: C2[64][64] = h1 @ W2, warp tile m32 x n32 ----
    float acc2[2][16];
    #pragma unroll
    for (int f = 0; f < 2; f++)
        #pragma unroll
        for (int i = 0; i < 16; i++) acc2[f][i] = 0.0f;
    {
        const uint32_t ab0 = smb + OFF_A23 + rowA0 * 256;
        const uint32_t ab1 = ab0 + 16 * 256;
        const unsigned char* wp2 = g_W2f + (size_t)wn * 8192 + lane * 16;

        uint4 bq[2][2];
        bq[0][0] = ldg_w(wp2);
        bq[0][1] = ldg_w(wp2 + 512);

        #pragma unroll
        for (int ks = 0; ks < 8; ks++) {
            const int cur = ks & 1, nxt = cur ^ 1;
            const uint32_t ao = (uint32_t)((2 * ks + kuA) ^ rxA) << 4;
            uint32_t a0, a1, a2, a3, a4, a5, a6, a7;
            ldsm4(a0, a1, a2, a3, ab0 + ao);
            ldsm4(a4, a5, a6, a7, ab1 + ao);
            if (ks < 7) {
                bq[nxt][0] = ldg_w(wp2 + (ks + 1) * 1024);
                bq[nxt][1] = ldg_w(wp2 + (ks + 1) * 1024 + 512);
            }
            const uint32_t* bb = (const uint32_t*)&bq[cur][0];
            #pragma unroll
            for (int j = 0; j < 4; j++)
                mma16816(&acc2[0][4*j], a0, a1, a2, a3, bb[2*j], bb[2*j+1]);
            #pragma unroll
            for (int j = 0; j < 4; j++)
                mma16816(&acc2[1][4*j], a4, a5, a6, a7, bb[2*j], bb[2*j+1]);
        }
    }

    // ---- epilogue2: score = relu(C2 + b2) . W3 (+b3) ----
    {
        float* part = (float*)(sm + OFF_PART);
        #pragma unroll
        for (int f = 0; f < 2; f++) {
            float p1 = 0.0f, p2 = 0.0f;
            #pragma unroll
            for (int j = 0; j < 4; j++) {
                const int col = wn * 32 + j * 8 + (lane & 3) * 2;
                const float ba = __ldg(b2 + col), bb = __ldg(b2 + col + 1);
                const float wa = __ldg(W3 + col), wwb = __ldg(W3 + col + 1);
                p1 += fmaxf(acc2[f][4*j]   + ba, 0.0f) * wa;
                p1 += fmaxf(acc2[f][4*j+1] + bb, 0.0f) * wwb;
                p2 += fmaxf(acc2[f][4*j+2] + ba, 0.0f) * wa;
                p2 += fmaxf(acc2[f][4*j+3] + bb, 0.0f) * wwb;
            }
            p1 += __shfl_xor_sync(0xffffffff, p1, 1);
            p1 += __shfl_xor_sync(0xffffffff, p1, 2);
            p2 += __shfl_xor_sync(0xffffffff, p2, 1);
            p2 += __shfl_xor_sync(0xffffffff, p2, 2);
            if ((lane & 3) == 0) {
                const int r1 = m0 + f * 16 + (lane >> 2);
                part[wn * 64 + r1]     = p1;
                part[wn * 64 + r1 + 8] = p2;
            }
        }
    }
    __syncthreads();
    if (tid < MB) {
        const float* part = (const float*)(sm + OFF_PART);
        const int e = eb + tid;
        if (e < E) out[e] = part[tid] + part[64 + tid] + __ldg(b3);
    }
}

// ---- launcher ----
extern "C" void kernel_launch(void* const* d_in, const int* in_sizes, int n_in,
                              void* d_out, int out_size)
{
    const float* z  = (const float*)d_in[0];
    const void*  ei = d_in[1];
    const float* W1 = (const float*)d_in[2];
    const float* b1 = (const float*)d_in[3];
    const float* W2 = (const float*)d_in[4];
    const float* b2 = (const float*)d_in[5];
    const float* W3 = (const float*)d_in[6];
    const float* b3 = (const float*)d_in[7];
    float* out = (float*)d_out;

    const int E = out_size;
    const int n_nodes = in_sizes[0] / HDIM;

    static bool attr_set = false;
    if (!attr_set) {
        cudaFuncSetAttribute(lp_main, cudaFuncAttributeMaxDynamicSharedMemorySize, SMEM_TOTAL);
        attr_set = true;
    }

    prep_weights<<<144, 256>>>(W1, W2, ei, E, n_nodes);

    const int grid = (E + MB - 1) / MB;
    lp_main<<<grid, THREADS, SMEM_TOTAL>>>(z, ei, b1, b2, W3, b3, out, E);
}

// round 15
// speedup vs baseline: 1.1031x; 1.1031x over previous
#include <cuda_runtime.h>
#include <cuda_fp16.h>
#include <cstdint>
#include <math.h>

// LinkPredictor via mma.sync (HMMA fp16 single-pass, fp32 accum).
// Round 15: round-13 config (MB=128, 256 thr, m32n64, B via coalesced LDG,
// 2 CTAs/SM) + W prefetch at phase entries, hoisted epilogue constants,
// unrolled chunk loop.
// Inputs: 0:z[500000*128]f32 1:edge_index[2*E] (i32 or i64)
//         2:W1[512*128] 3:b1[128] 4:W2[128*64] 5:b2[64] 6:W3[64] 7:b3[1]
// Output: score[E] f32

#define HDIM 128
constexpr int MB      = 128;
constexpr int THREADS = 256;   // 8 warps: 4m x 2n, warp tile m32 x n64

// ---- smem layout ----
constexpr int OFF_PART = 0;          // 1024 B
constexpr int PLANE    = 32768;      // 128 rows * 256 B
constexpr int OFF_SRC  = 1024;
constexpr int OFF_DST  = OFF_SRC + PLANE;    // 33792
constexpr int OFF_A23  = OFF_DST + PLANE;    // 66560
constexpr int SMEM_TOTAL = OFF_A23 + PLANE;  // 99328 -> 2 CTAs/SM

// fragment-ordered, warp-coalesced weight images
// W1f word idx: [c:4][wn:2][ks:8][t:4][lane:32][r2:4] -> 131072 B
// W2f word idx: [wn:2][ks:8][t:2][lane:32][r2:4]      -> 16384 B
__device__ unsigned char g_W1f[131072];
__device__ unsigned char g_W2f[16384];
__device__ int g_ei_is64;

// ---- helpers ----
__device__ __forceinline__ uint32_t smem_u32(const void* p) {
    uint32_t a;
    asm("{ .reg .u64 t; cvta.to.shared.u64 t, %1; cvt.u32.u64 %0, t; }" : "=r"(a) : "l"(p));
    return a;
}
__device__ __forceinline__ void ldsm4(uint32_t& r0, uint32_t& r1, uint32_t& r2, uint32_t& r3,
                                      uint32_t addr) {
    asm volatile("ldmatrix.sync.aligned.m8n8.x4.shared.b16 {%0,%1,%2,%3}, [%4];"
        : "=r"(r0), "=r"(r1), "=r"(r2), "=r"(r3) : "r"(addr));
}
__device__ __forceinline__ void mma16816(float* c, uint32_t a0, uint32_t a1, uint32_t a2,
                                         uint32_t a3, uint32_t b0, uint32_t b1) {
    asm volatile("mma.sync.aligned.m16n8k16.row.col.f32.f16.f16.f32 "
        "{%0,%1,%2,%3}, {%4,%5,%6,%7}, {%8,%9}, {%0,%1,%2,%3};"
        : "+f"(c[0]), "+f"(c[1]), "+f"(c[2]), "+f"(c[3])
        : "r"(a0), "r"(a1), "r"(a2), "r"(a3), "r"(b0), "r"(b1));
}
__device__ __forceinline__ float4 ldg_ef(const float* p) {
    float4 v;
    asm volatile("ld.global.L1::evict_first.v4.f32 {%0,%1,%2,%3}, [%4];"
        : "=f"(v.x), "=f"(v.y), "=f"(v.z), "=f"(v.w) : "l"(p));
    return v;
}
__device__ __forceinline__ uint4 ldg_w(const unsigned char* p) {
    uint4 v;
    asm volatile("ld.global.nc.L1::evict_last.v4.u32 {%0,%1,%2,%3}, [%4];"
        : "=r"(v.x), "=r"(v.y), "=r"(v.z), "=r"(v.w) : "l"(p));
    return v;
}
__device__ __forceinline__ void pref_l1(const void* p) {
    asm volatile("prefetch.global.L1 [%0];" :: "l"(p));
}

__device__ __host__ __forceinline__ uint32_t aoff(int row, int k) {
    return (uint32_t)(row * 256 + (((k >> 3) ^ (row & 7)) << 4) + (k & 7) * 2);
}
__device__ __forceinline__ uint2 pack4h(float4 v) {
    uint2 r;
    __half2 p0 = __floats2half2_rn(v.x, v.y);
    __half2 p1 = __floats2half2_rn(v.z, v.w);
    r.x = *(uint32_t*)&p0;
    r.y = *(uint32_t*)&p1;
    return r;
}
__device__ __forceinline__ float hfr(uint32_t w, int hi16) {
    return __half2float(__ushort_as_half((uint16_t)(hi16 ? (w >> 16) : (w & 0xffff))));
}

// ---- setup kernel: coalesced fragment-order weights + dtype detect ----
__global__ void prep_weights(const float* __restrict__ W1, const float* __restrict__ W2,
                             const void* ei, int E, int n_nodes) {
    if (blockIdx.x == 0 && threadIdx.x == 0) {
        const long long* e64 = (const long long*)ei;
        int n = (E < 64) ? E : 64;
        int is64 = 1;
        for (int i = 0; i < n; i++) {
            long long v = e64[i];
            if (v < 0 || v >= (long long)n_nodes) { is64 = 0; break; }
        }
        g_ei_is64 = is64;
    }
    int idx = blockIdx.x * 256 + threadIdx.x;
    if (idx < 32768) {
        int r2 = idx & 3, lane = (idx >> 2) & 31, t = (idx >> 7) & 3;
        int ks = (idx >> 9) & 7, wn = (idx >> 12) & 1, c = (idx >> 13) & 3;
        int j = t * 2 + (r2 >> 1), r = r2 & 1;
        int n = wn * 64 + j * 8 + (lane >> 2);
        int k = c * 128 + ks * 16 + (lane & 3) * 2 + r * 8;
        __half2 p = __floats2half2_rn(W1[k * 128 + n], W1[(k + 1) * 128 + n]);
        *(uint32_t*)(g_W1f + (size_t)idx * 4) = *(uint32_t*)&p;
    } else if (idx < 32768 + 4096) {
        int i2 = idx - 32768;
        int r2 = i2 & 3, lane = (i2 >> 2) & 31, t = (i2 >> 7) & 1;
        int ks = (i2 >> 8) & 7, wn = (i2 >> 11) & 1;
        int j = t * 2 + (r2 >> 1), r = r2 & 1;
        int n = wn * 32 + j * 8 + (lane >> 2);
        int k = ks * 16 + (lane & 3) * 2 + r * 8;
        __half2 p = __floats2half2_rn(W2[k * 64 + n], W2[(k + 1) * 64 + n]);
        *(uint32_t*)(g_W2f + (size_t)i2 * 4) = *(uint32_t*)&p;
    }
}

// ---- main kernel ----
__global__ __launch_bounds__(THREADS, 2)
void lp_main(const float* __restrict__ z,
             const void* __restrict__ ei_raw,
             const float* __restrict__ b1,
             const float* __restrict__ b2,
             const float* __restrict__ W3,
             const float* __restrict__ b3,
             float* __restrict__ out,
             int E)
{
    extern __shared__ unsigned char sm[];
    const uint32_t smb = smem_u32(sm);
    const int tid  = threadIdx.x;
    const int warp = tid >> 5;
    const int lane = tid & 31;
    const int wm = warp >> 1, wn = warp & 1;
    const int m0 = wm * 32;
    const int eb = blockIdx.x * MB;

    // warm L1 with this warp's chunk-0 W fragments (no register cost)
    {
        const unsigned char* wp0 = g_W1f + (size_t)(wn * 16384) + lane * 16;
        #pragma unroll
        for (int t = 0; t < 4; t++) pref_l1(wp0 + t * 512);
    }

    // hoist epilogue-2 constants (independent loads, hide under gather)
    float eb2[8], ew3[8];
    #pragma unroll
    for (int j = 0; j < 4; j++) {
        const int col = wn * 32 + j * 8 + (lane & 3) * 2;
        eb2[2*j]   = __ldg(b2 + col);     eb2[2*j+1] = __ldg(b2 + col + 1);
        ew3[2*j]   = __ldg(W3 + col);     ew3[2*j+1] = __ldg(W3 + col + 1);
    }
    const float bias3 = __ldg(b3);

    // ---- gather: 16 edges per warp, high-MLP ----
    {
        const int is64 = g_ei_is64;
        const long long* e64 = (const long long*)ei_raw;
        const int*       e32 = (const int*)ei_raw;

        int si[16], di[16];
        #pragma unroll
        for (int i = 0; i < 16; i++) {
            const int e = eb + warp * 16 + i;
            const int ec = (e < E) ? e : (E - 1);
            if (is64) { si[i] = (int)e64[ec]; di[i] = (int)e64[(size_t)E + ec]; }
            else      { si[i] = e32[ec];      di[i] = e32[(size_t)E + ec]; }
        }

        #pragma unroll
        for (int ib = 0; ib < 4; ib++) {
            float4 sv[4], dv[4];
            #pragma unroll
            for (int j = 0; j < 4; j++) {
                sv[j] = ldg_ef(z + (size_t)si[ib * 4 + j] * HDIM + lane * 4);
                dv[j] = ldg_ef(z + (size_t)di[ib * 4 + j] * HDIM + lane * 4);
            }
            #pragma unroll
            for (int j = 0; j < 4; j++) {
                const int r = warp * 16 + ib * 4 + j;
                float4 iv;
                iv.x = sv[j].x * dv[j].x; iv.y = sv[j].y * dv[j].y;
                iv.z = sv[j].z * dv[j].z; iv.w = sv[j].w * dv[j].w;
                const uint32_t o = aoff(r, lane * 4);
                *(uint2*)(sm + OFF_SRC + o) = pack4h(sv[j]);
                *(uint2*)(sm + OFF_DST + o) = pack4h(dv[j]);
                *(uint2*)(sm + OFF_A23 + o) = pack4h(iv);
            }
        }
    }
    __syncthreads();

    // ---- A-side ldmatrix geometry (m32 via two m16 frags) ----
    const int tileA = lane >> 3;
    const int rowA0 = m0 + ((tileA & 1) << 3) + (lane & 7);
    const int rxA   = rowA0 & 7;
    const int kuA   = tileA >> 1;

    float acc[2][32];
    #pragma unroll
    for (int f = 0; f < 2; f++)
        #pragma unroll
        for (int i = 0; i < 32; i++) acc[f][i] = 0.0f;

    static const int AOFS[4] = {OFF_SRC, OFF_DST, OFF_A23, OFF_A23};

    // ---- GEMM1: 4 K-chunks of 128; B via coalesced LDG, double-buffered ----
    #pragma unroll
    for (int c = 0; c < 4; c++) {
        if (c == 3) {        // rebuild A23 = |src-dst| (prod reads done)
            __syncthreads();
            #pragma unroll
            for (int t = 0; t < 8; t++) {
                const int idx = tid + t * 256;
                const int r = idx >> 4, kg = (idx & 15) * 8;
                const uint32_t o = aoff(r, kg);
                const uint4 shv = *(const uint4*)(sm + OFF_SRC + o);
                const uint4 dhv = *(const uint4*)(sm + OFF_DST + o);
                uint4 rv;
                const uint32_t* sp = &shv.x;
                const uint32_t* dp = &dhv.x;
                uint32_t* rp = &rv.x;
                #pragma unroll
                for (int q = 0; q < 4; q++) {
                    float a0 = fabsf(hfr(sp[q],0) - hfr(dp[q],0));
                    float a1 = fabsf(hfr(sp[q],1) - hfr(dp[q],1));
                    __half2 p = __floats2half2_rn(a0, a1);
                    rp[q] = *(uint32_t*)&p;
                }
                *(uint4*)(sm + OFF_A23 + o) = rv;
            }
            __syncthreads();
        }

        const uint32_t ab0 = smb + AOFS[c] + rowA0 * 256;
        const uint32_t ab1 = ab0 + 16 * 256;
        const unsigned char* wp = g_W1f + (size_t)(c * 2 + wn) * 16384 + lane * 16;

        uint4 bq[2][4];
        #pragma unroll
        for (int t = 0; t < 4; t++) bq[0][t] = ldg_w(wp + t * 512);

        #pragma unroll
        for (int ks = 0; ks < 8; ks++) {
            const int cur = ks & 1, nxt = cur ^ 1;
            const uint32_t ao = (uint32_t)((2 * ks + kuA) ^ rxA) << 4;
            uint32_t a0, a1, a2, a3, a4, a5, a6, a7;
            ldsm4(a0, a1, a2, a3, ab0 + ao);
            ldsm4(a4, a5, a6, a7, ab1 + ao);
            if (ks < 7) {
                #pragma unroll
                for (int t = 0; t < 4; t++)
                    bq[nxt][t] = ldg_w(wp + (ks + 1) * 2048 + t * 512);
            } else if (c < 3) {
                // warm L1 for next chunk's first fragments
                const unsigned char* wpn = wp + 16384;
                #pragma unroll
                for (int t = 0; t < 4; t++) pref_l1(wpn + t * 512);
            } else {
                const unsigned char* wp2 = g_W2f + (size_t)wn * 8192 + lane * 16;
                pref_l1(wp2); pref_l1(wp2 + 512);
            }
            const uint32_t* bb = (const uint32_t*)&bq[cur][0];
            #pragma unroll
            for (int j = 0; j < 8; j++)
                mma16816(&acc[0][4*j], a0, a1, a2, a3, bb[2*j], bb[2*j+1]);
            #pragma unroll
            for (int j = 0; j < 8; j++)
                mma16816(&acc[1][4*j], a4, a5, a6, a7, bb[2*j], bb[2*j+1]);
        }
    }

    // ---- epilogue1: h1 = relu(C1 + b1) -> fp16 into A23 ----
    __syncthreads();
    {
        #pragma unroll
        for (int f = 0; f < 2; f++) {
            const int r1 = m0 + f * 16 + (lane >> 2);
            #pragma unroll
            for (int j = 0; j < 8; j++) {
                const int col = wn * 64 + j * 8 + (lane & 3) * 2;
                const float ba = __ldg(b1 + col), bb = __ldg(b1 + col + 1);
                __half2 p0 = __floats2half2_rn(fmaxf(acc[f][4*j]   + ba, 0.0f),
                                               fmaxf(acc[f][4*j+1] + bb, 0.0f));
                __half2 p1 = __floats2half2_rn(fmaxf(acc[f][4*j+2] + ba, 0.0f),
                                               fmaxf(acc[f][4*j+3] + bb, 0.0f));
                *(uint32_t*)(sm + OFF_A23 + aoff(r1, col))     = *(uint32_t*)&p0;
                *(uint32_t*)(sm + OFF_A23 + aoff(r1 + 8, col)) = *(uint32_t*)&p1;
            }
        }
    }
    __syncthreads();

    // ---- GEMM2: C2[128][64] = h1 @ W2, warp tile m32 x n32 ----
    float acc2[2][16];
    #pragma unroll
    for (int f = 0; f < 2; f++)
        #pragma unroll
        for (int i = 0; i < 16; i++) acc2[f][i] = 0.0f;
    {
        const uint32_t ab0 = smb + OFF_A23 + rowA0 * 256;
        const uint32_t ab1 = ab0 + 16 * 256;
        const unsigned char* wp2 = g_W2f + (size_t)wn * 8192 + lane * 16;

        uint4 bq[2][2];
        bq[0][0] = ldg_w(wp2);
        bq[0][1] = ldg_w(wp2 + 512);

        #pragma unroll
        for (int ks = 0; ks < 8; ks++) {
            const int cur = ks & 1, nxt = cur ^ 1;
            const uint32_t ao = (uint32_t)((2 * ks + kuA) ^ rxA) << 4;
            uint32_t a0, a1, a2, a3, a4, a5, a6, a7;
            ldsm4(a0, a1, a2, a3, ab0 + ao);
            ldsm4(a4, a5, a6, a7, ab1 + ao);
            if (ks < 7) {
                bq[nxt][0] = ldg_w(wp2 + (ks + 1) * 1024);
                bq[nxt][1] = ldg_w(wp2 + (ks + 1) * 1024 + 512);
            }
            const uint32_t* bb = (const uint32_t*)&bq[cur][0];
            #pragma unroll
            for (int j = 0; j < 4; j++)
                mma16816(&acc2[0][4*j], a0, a1, a2, a3, bb[2*j], bb[2*j+1]);
            #pragma unroll
            for (int j = 0; j < 4; j++)
                mma16816(&acc2[1][4*j], a4, a5, a6, a7, bb[2*j], bb[2*j+1]);
        }
    }

    // ---- epilogue2: score = relu(C2 + b2) . W3 (+b3) ----
    {
        float* part = (float*)(sm + OFF_PART);
        #pragma unroll
        for (int f = 0; f < 2; f++) {
            float p1 = 0.0f, p2 = 0.0f;
            #pragma unroll
            for (int j = 0; j < 4; j++) {
                p1 += fmaxf(acc2[f][4*j]   + eb2[2*j],   0.0f) * ew3[2*j];
                p1 += fmaxf(acc2[f][4*j+1] + eb2[2*j+1], 0.0f) * ew3[2*j+1];
                p2 += fmaxf(acc2[f][4*j+2] + eb2[2*j],   0.0f) * ew3[2*j];
                p2 += fmaxf(acc2[f][4*j+3] + eb2[2*j+1], 0.0f) * ew3[2*j+1];
            }
            p1 += __shfl_xor_sync(0xffffffff, p1, 1);
            p1 += __shfl_xor_sync(0xffffffff, p1, 2);
            p2 += __shfl_xor_sync(0xffffffff, p2, 1);
            p2 += __shfl_xor_sync(0xffffffff, p2, 2);
            if ((lane & 3) == 0) {
                const int r1 = m0 + f * 16 + (lane >> 2);
                part[wn * 128 + r1]     = p1;
                part[wn * 128 + r1 + 8] = p2;
            }
        }
    }
    __syncthreads();
    if (tid < MB) {
        const float* part = (const float*)(sm + OFF_PART);
        const int e = eb + tid;
        if (e < E) out[e] = part[tid] + part[128 + tid] + bias3;
    }
}

// ---- launcher ----
extern "C" void kernel_launch(void* const* d_in, const int* in_sizes, int n_in,
                              void* d_out, int out_size)
{
    const float* z  = (const float*)d_in[0];
    const void*  ei = d_in[1];
    const float* W1 = (const float*)d_in[2];
    const float* b1 = (const float*)d_in[3];
    const float* W2 = (const float*)d_in[4];
    const float* b2 = (const float*)d_in[5];
    const float* W3 = (const float*)d_in[6];
    const float* b3 = (const float*)d_in[7];
    float* out = (float*)d_out;

    const int E = out_size;
    const int n_nodes = in_sizes[0] / HDIM;

    static bool attr_set = false;
    if (!attr_set) {
        cudaFuncSetAttribute(lp_main, cudaFuncAttributeMaxDynamicSharedMemorySize, SMEM_TOTAL);
        attr_set = true;
    }

    prep_weights<<<144, 256>>>(W1, W2, ei, E, n_nodes);

    const int grid = (E + MB - 1) / MB;
    lp_main<<<grid, THREADS, SMEM_TOTAL>>>(z, ei, b1, b2, W3, b3, out, E);
}